// round 12
// baseline (speedup 1.0000x reference)
#include <cuda_runtime.h>
#include <cuda_bf16.h>

// RWKV single-token inference, fp32 — persistent kernel 148x512 (16 warps/SM).
// R12: per-warp bandwidth is capped (~2.5GB/s); scale concurrent streaming
// warps. k/v/r matvecs split one-row-per-warp (epilogue in its own phase),
// ow/fvw rows split across warp pairs. Block-strided ids spread work over SMs.
// cp.async 3-slot pipeline, uniform commit/wait ledger.

#define D    1024
#define HD   4096
#define NL   24
#define NV   50277
#define GRID 148
#define NTH  512
#define NWARP 16
#define TOTW (GRID * NWARP)   // 2368

#define SBUF_F   4096                  // 16KB shared vector region (floats)
#define WSLOT_F  1024                  // 4KB per slot
#define NSLOT    3
#define SMEM_DYN ((SBUF_F + NWARP * NSLOT * WSLOT_F) * 4)   // 208KB

__device__ __align__(16) float g_x[D];
__device__ __align__(16) float g_rwkv[D];
__device__ __align__(16) float g_kvr[3 * D];    // k | v | r matvec results
__device__ __align__(16) float g_kk[HD];
__device__ __align__(16) float g_r2[D];
__device__ __align__(16) float g_state_scratch[NL * 5 * D];
__device__ unsigned g_count;
__device__ unsigned g_gen;

__device__ __forceinline__ float warp_sum(float s) {
#pragma unroll
    for (int o = 16; o > 0; o >>= 1) s += __shfl_xor_sync(0xffffffffu, s, o);
    return s;
}

__device__ __forceinline__ float block_sum512(float v, float* sred) {
    __syncthreads();
    v = warp_sum(v);
    int warp = threadIdx.x >> 5, lane = threadIdx.x & 31;
    if (lane == 0) sred[warp] = v;
    __syncthreads();
    float t = 0.f;
#pragma unroll
    for (int w = 0; w < NWARP; w++) t += sred[w];
    return t;
}

// Grid barrier, acq/rel atomics (148 blocks co-resident, 1 CTA/SM).
__device__ __forceinline__ void grid_barrier() {
    __syncthreads();
    if (threadIdx.x == 0) {
        unsigned gen;
        asm volatile("ld.global.relaxed.gpu.u32 %0, [%1];" : "=r"(gen) : "l"(&g_gen));
        unsigned old;
        asm volatile("atom.global.add.acq_rel.gpu.u32 %0, [%1], 1;"
                     : "=r"(old) : "l"(&g_count) : "memory");
        if (old == GRID - 1) {
            asm volatile("st.global.relaxed.gpu.u32 [%0], %1;" :: "l"(&g_count), "r"(0u) : "memory");
            asm volatile("st.global.release.gpu.u32 [%0], %1;" :: "l"(&g_gen), "r"(gen + 1u) : "memory");
        } else {
            unsigned cur;
            do {
                __nanosleep(20);
                asm volatile("ld.global.acquire.gpu.u32 %0, [%1];" : "=r"(cur) : "l"(&g_gen) : "memory");
            } while (cur == gen);
        }
    }
    __syncthreads();
}

#define PAIR_BAR(pl) asm volatile("bar.sync %0, %1;" :: "r"(1 + (pl)), "r"(64) : "memory")

// 4KB row (1024 floats) -> shared, 8x16B per lane.
__device__ __forceinline__ void cpa_row(unsigned dst, const float* __restrict__ src, int lane) {
    unsigned d = dst + (unsigned)lane * 16u;
    const char* s = (const char*)src + lane * 16;
#pragma unroll
    for (int j = 0; j < 8; j++)
        asm volatile("cp.async.cg.shared.global [%0], [%1], 16;"
                     :: "r"(d + 512u * j), "l"(s + 512 * j) : "memory");
}
// 2KB half-row (512 floats) -> shared, 4x16B per lane.
__device__ __forceinline__ void cpa_half(unsigned dst, const float* __restrict__ src, int lane) {
    unsigned d = dst + (unsigned)lane * 16u;
    const char* s = (const char*)src + lane * 16;
#pragma unroll
    for (int j = 0; j < 4; j++)
        asm volatile("cp.async.cg.shared.global [%0], [%1], 16;"
                     :: "r"(d + 512u * j), "l"(s + 512 * j) : "memory");
}
#define CPA_COMMIT() asm volatile("cp.async.commit_group;" ::: "memory")
#define CPA_WAIT(n)  asm volatile("cp.async.wait_group %0;" :: "n"(n) : "memory")

__device__ __forceinline__ float dot_ss(const float4* __restrict__ w4,
                                        const float4* __restrict__ v4, int lane) {
    float s = 0.f;
#pragma unroll
    for (int j = 0; j < 8; j++) {
        float4 a = w4[lane + 32 * j];
        float4 b = v4[lane + 32 * j];
        s = fmaf(a.x, b.x, s); s = fmaf(a.y, b.y, s);
        s = fmaf(a.z, b.z, s); s = fmaf(a.w, b.w, s);
    }
    return s;
}
__device__ __forceinline__ float dot_half(const float4* __restrict__ w4,
                                          const float4* __restrict__ v4, int lane) {
    float s = 0.f;
#pragma unroll
    for (int j = 0; j < 4; j++) {
        float4 a = w4[lane + 32 * j];
        float4 b = v4[lane + 32 * j];
        s = fmaf(a.x, b.x, s); s = fmaf(a.y, b.y, s);
        s = fmaf(a.z, b.z, s); s = fmaf(a.w, b.w, s);
    }
    return s;
}

// LN over g_x; 512 threads, 2 outputs per thread.
__device__ __forceinline__ void ln512(const float* __restrict__ w,
                                      const float* __restrict__ b,
                                      float* sred, float& o0, float& o1) {
    int t = threadIdx.x;
    float2 xv = __ldcg((const float2*)g_x + t);
    float mu = block_sum512(xv.x + xv.y, sred) * (1.f / D);
    float d0 = xv.x - mu, d1 = xv.y - mu;
    float var = block_sum512(d0 * d0 + d1 * d1, sred) * (1.f / D);
    float rstd = rsqrtf(var + 1e-5f);
    float2 wv = ((const float2*)w)[t];
    float2 bv = ((const float2*)b)[t];
    o0 = d0 * rstd * wv.x + bv.x;
    o1 = d1 * rstd * wv.y + bv.y;
}

__global__ __launch_bounds__(NTH, 1) void rwkv_fused(
    const int* __restrict__ token, const float* __restrict__ state,
    const float* __restrict__ emb,
    const float* __restrict__ ln0_w, const float* __restrict__ ln0_b,
    const float* __restrict__ ln1_w, const float* __restrict__ ln1_b,
    const float* __restrict__ ln2_w, const float* __restrict__ ln2_b,
    const float* __restrict__ kw, const float* __restrict__ vw,
    const float* __restrict__ rw, const float* __restrict__ ow,
    const float* __restrict__ mk, const float* __restrict__ mv,
    const float* __restrict__ mr,
    const float* __restrict__ tf, const float* __restrict__ td,
    const float* __restrict__ fkw, const float* __restrict__ fvw,
    const float* __restrict__ frw,
    const float* __restrict__ fmk, const float* __restrict__ fmr,
    const float* __restrict__ lnw, const float* __restrict__ lnb,
    const float* __restrict__ head,
    float* __restrict__ logits, float* __restrict__ state_out) {
    __shared__ float sred[NWARP];
    __shared__ float s_part[NWARP];
    extern __shared__ __align__(16) float dsm[];
    float* s_buf = dsm;                                             // 16KB
    float* wbuf  = dsm + SBUF_F + (threadIdx.x >> 5) * (NSLOT * WSLOT_F);
    const unsigned wb_u32 = (unsigned)__cvta_generic_to_shared(wbuf);

    const int t = threadIdx.x, warp = t >> 5, lane = t & 31, bid = blockIdx.x;
    const int pl = warp >> 1, h = warp & 1;
    const int wgS   = warp * GRID + bid;        // 0..2367, block-strided
    const int pairS = pl * GRID + bid;          // 0..1183
    const bool rowact = (pairS < D);            // pair owns row pairS in B/D

#define SLOT_PTR(i) ((const float4*)(wbuf + (i) * WSLOT_F))
#define SLOT_U32(i) (wb_u32 + (unsigned)(i) * 4096u)

    // Phase A units: u1 = wgS (mat=wgS>>10,row=wgS&1023); u2 = wgS+2368 (if wgS<704)
    const int matA = wgS >> 10, rowA = wgS & 1023;
    const bool hasA2 = (wgS < 3 * D - TOTW);    // wgS < 704
    const int rowA2 = wgS + 320;                // mat 2 (r)

    // Phase C units
    const int c2 = wgS + TOTW;                  // 2368..4735
    const bool c2fk = (c2 < HD);
    const bool hasC3 = (wgS < (HD + D) - 2 * TOTW);   // wgS < 384
    const int rowC3 = wgS + 640;                // frw row

    // ---- embed: block 0 computes g_x = LN0(emb[token]) ----
    if (bid == 0) {
        float2 xv = ((const float2*)(emb + (size_t)token[0] * D))[t];
        float mu = block_sum512(xv.x + xv.y, sred) * (1.f / D);
        float d0 = xv.x - mu, d1 = xv.y - mu;
        float var = block_sum512(d0 * d0 + d1 * d1, sred) * (1.f / D);
        float rstd = rsqrtf(var + 1e-5f);
        float2 wv = ((const float2*)ln0_w)[t];
        float2 bv = ((const float2*)ln0_b)[t];
        float2 o;
        o.x = d0 * rstd * wv.x + bv.x;
        o.y = d1 * rstd * wv.y + bv.y;
        ((float2*)g_x)[t] = o;
    }

    for (int l = 0; l < NL; l++) {
        const size_t lo = (size_t)l * D;
        const size_t sb = (size_t)l * 5 * D;
        const float* fk_base = fkw + (size_t)l * HD * D;
        const float* fr_base = frw + lo * D;
        const float* fv_row  = fvw + (size_t)l * D * HD + (size_t)pairS * HD;

        // ---- layer top: commits #1 (A1) and #2 (A2|dummy) ----
        const float* matp = (matA == 0) ? kw : (matA == 1) ? vw : rw;
        cpa_row(SLOT_U32(0), matp + lo * D + (size_t)rowA * D, lane); CPA_COMMIT();
        if (hasA2) cpa_row(SLOT_U32(1), rw + lo * D + (size_t)rowA2 * D, lane);
        CPA_COMMIT();
        // pending: {1,2}

        // ================= Phase A: k/v/r matvecs =================
        grid_barrier();   // g_x final
        {
            float xn0, xn1;
            ln512(ln1_w + lo, ln1_b + lo, sred, xn0, xn1);
            float2 mk2 = ((const float2*)(mk + lo))[t];
            float2 mv2 = ((const float2*)(mv + lo))[t];
            float2 mr2 = ((const float2*)(mr + lo))[t];
            float2 sx2 = ((const float2*)(state + sb + D))[t];   // sx_att
            s_buf[2 * t]             = xn0 * mk2.x + sx2.x * (1.f - mk2.x);
            s_buf[2 * t + 1]         = xn1 * mk2.y + sx2.y * (1.f - mk2.y);
            s_buf[D + 2 * t]         = xn0 * mv2.x + sx2.x * (1.f - mv2.x);
            s_buf[D + 2 * t + 1]     = xn1 * mv2.y + sx2.y * (1.f - mv2.y);
            s_buf[2 * D + 2 * t]     = xn0 * mr2.x + sx2.x * (1.f - mr2.x);
            s_buf[2 * D + 2 * t + 1] = xn1 * mr2.y + sx2.y * (1.f - mr2.y);
            if (bid == 0) {                       // state row 1 = xn
                state_out[sb + D + 2 * t]     = xn0;
                state_out[sb + D + 2 * t + 1] = xn1;
            }
            __syncthreads();

            CPA_WAIT(1);   // A1 landed; pending {2}
            {
                float s = warp_sum(dot_ss(SLOT_PTR(0),
                                          (const float4*)(s_buf + matA * D), lane));
                if (lane == 0) g_kvr[wgS] = s;
            }
            // commit #3: B half-row | dummy
            if (rowact) cpa_half(SLOT_U32(2), ow + lo * D + (size_t)pairS * D
                                              + (size_t)h * 512, lane);
            CPA_COMMIT();  // pending {2,3}
            CPA_WAIT(1);   // A2 landed; pending {3}
            if (hasA2) {
                float s = warp_sum(dot_ss(SLOT_PTR(1),
                                          (const float4*)(s_buf + 2 * D), lane));
                if (lane == 0) g_kvr[wgS + TOTW] = s;
            }
            // commit #4: C1 (always; wgS < 4096 -> fkw)
            cpa_row(SLOT_U32(0), fk_base + (size_t)wgS * D, lane);
            CPA_COMMIT();  // pending {3,4}
        }

        // ================= Phase E: WKV epilogue =================
        grid_barrier();   // g_kvr complete
        {
            int r = t * GRID + bid;
            if (t < 7 && r < D) {
                float k  = __ldcg(&g_kvr[r]);
                float v  = __ldcg(&g_kvr[D + r]);
                float sr = __ldcg(&g_kvr[2 * D + r]);
                float aa = state[sb + 2 * D + r];
                float bb = state[sb + 3 * D + r];
                float pp = state[sb + 4 * D + r];
                float tfv = tf[lo + r];
                float tdv = td[lo + r];
                float rs = 1.f / (1.f + expf(-sr));

                float ww = tfv + k;
                float qq = fmaxf(pp, ww);
                float e1 = expf(pp - qq);
                float e2 = expf(ww - qq);
                g_rwkv[r] = rs * (e1 * aa + e2 * v) / (e1 * bb + e2);

                float ww2 = pp + tdv;
                float qq2 = fmaxf(ww2, k);
                float e1b = expf(ww2 - qq2);
                float e2b = expf(k - qq2);
                state_out[sb + 2 * D + r] = e1b * aa + e2b * v;
                state_out[sb + 3 * D + r] = e1b * bb + e2b;
                state_out[sb + 4 * D + r] = qq2;
            }
            // commit #5: C2 (always valid)
            cpa_row(SLOT_U32(1), c2fk ? fk_base + (size_t)c2 * D
                                      : fr_base + (size_t)(c2 - HD) * D, lane);
            CPA_COMMIT();  // pending {3,4,5}
        }

        // ================= Phase B: x += ow @ rwkv (pair split) =================
        grid_barrier();   // g_rwkv complete
        {
            ((float2*)s_buf)[t] = __ldcg((const float2*)g_rwkv + t);
            __syncthreads();
            CPA_WAIT(2);   // B half landed; pending {4,5}
            if (rowact) {
                float s = warp_sum(dot_half(SLOT_PTR(2),
                                            (const float4*)s_buf + h * 128, lane));
                if (lane == 0) s_part[warp] = s;
                PAIR_BAR(pl);
                if (h == 0 && lane == 0) {
                    float tot = s_part[warp] + s_part[warp + 1];
                    g_x[pairS] = __ldcg(g_x + pairS) + tot;
                }
            }
            // commit #6: C3 | dummy
            if (hasC3) cpa_row(SLOT_U32(2), fr_base + (size_t)rowC3 * D, lane);
            CPA_COMMIT();  // pending {4,5,6}
        }

        // ================= Phase C: channel mix 1 =================
        grid_barrier();   // g_x updated
        {
            float xn0, xn1;
            ln512(ln2_w + lo, ln2_b + lo, sred, xn0, xn1);
            float2 mk2 = ((const float2*)(fmk + lo))[t];
            float2 mr2 = ((const float2*)(fmr + lo))[t];
            float2 sx2 = ((const float2*)(state + sb))[t];       // sx_ffn
            s_buf[2 * t]         = xn0 * mk2.x + sx2.x * (1.f - mk2.x);
            s_buf[2 * t + 1]     = xn1 * mk2.y + sx2.y * (1.f - mk2.y);
            s_buf[D + 2 * t]     = xn0 * mr2.x + sx2.x * (1.f - mr2.x);
            s_buf[D + 2 * t + 1] = xn1 * mr2.y + sx2.y * (1.f - mr2.y);
            if (bid == 0) {                      // state row 0 = xn2
                state_out[sb + 2 * t]     = xn0;
                state_out[sb + 2 * t + 1] = xn1;
            }
            __syncthreads();

            const float4* xk4 = (const float4*)s_buf;
            const float4* xr4 = (const float4*)(s_buf + D);

            CPA_WAIT(2);   // C1 landed; pending {5,6}
            {
                float s = warp_sum(dot_ss(SLOT_PTR(0), xk4, lane));
                if (lane == 0) { float rl = fmaxf(s, 0.f); g_kk[wgS] = rl * rl; }
            }
            // commit #7: D chunk1 | dummy
            if (rowact) cpa_row(SLOT_U32(0), fv_row + (size_t)(2 * h) * 1024, lane);
            CPA_COMMIT();  // pending {5,6,7}

            CPA_WAIT(2);   // C2 landed; pending {6,7}
            {
                float s = warp_sum(dot_ss(SLOT_PTR(1), c2fk ? xk4 : xr4, lane));
                if (lane == 0) {
                    if (c2fk) { float rl = fmaxf(s, 0.f); g_kk[c2] = rl * rl; }
                    else g_r2[c2 - HD] = 1.f / (1.f + expf(-s));
                }
            }
            // commit #8: D chunk2 | dummy
            if (rowact) cpa_row(SLOT_U32(1), fv_row + (size_t)(2 * h + 1) * 1024, lane);
            CPA_COMMIT();  // pending {6,7,8}

            CPA_WAIT(2);   // C3 landed; pending {7,8}
            if (hasC3) {
                float s = warp_sum(dot_ss(SLOT_PTR(2), xr4, lane));
                if (lane == 0) g_r2[rowC3] = 1.f / (1.f + expf(-s));
            }
        }

        // ================= Phase D: x += r2 * (fvw @ kk) =================
        grid_barrier();   // g_kk, g_r2 complete
        {
            ((float4*)s_buf)[t]       = __ldcg((const float4*)g_kk + t);
            ((float4*)s_buf)[t + NTH] = __ldcg((const float4*)g_kk + t + NTH);
            __syncthreads();
            const float4* k4 = (const float4*)s_buf;
            CPA_WAIT(1);   // D1 landed; pending {8}
            float s = 0.f;
            if (rowact) s = dot_ss(SLOT_PTR(0), k4 + (2 * h) * 256, lane);
            CPA_WAIT(0);   // D2 landed; pending {}
            if (rowact) {
                s += dot_ss(SLOT_PTR(1), k4 + (2 * h + 1) * 256, lane);
                s = warp_sum(s);
                if (lane == 0) s_part[warp] = s;
                PAIR_BAR(pl);
                if (h == 0 && lane == 0) {
                    float tot = s_part[warp] + s_part[warp + 1];
                    g_x[pairS] = __ldcg(g_x + pairS) + __ldcg(g_r2 + pairS) * tot;
                }
            }
        }
    }

    // ================= Head: logits = head @ LN(x) =================
#pragma unroll
    for (int i = 0; i < NSLOT; i++) {   // wgS + 2*TOTW = 7103 < NV always
        cpa_row(SLOT_U32(i), head + (size_t)(wgS + i * TOTW) * D, lane);
        CPA_COMMIT();
    }   // pending 3
    grid_barrier();   // g_x final
    {
        float xn0, xn1;
        ln512(lnw, lnb, sred, xn0, xn1);
        s_buf[2 * t]     = xn0;
        s_buf[2 * t + 1] = xn1;
        __syncthreads();

        const float4* x4 = (const float4*)s_buf;
        int i = 0;
        for (int v = wgS; v < NV; v += TOTW, i++) {
            CPA_WAIT(2);   // oldest of 3 done
            int slot = i % NSLOT;
            float s = warp_sum(dot_ss(SLOT_PTR(slot), x4, lane));
            int vn = v + NSLOT * TOTW;
            if (vn < NV) cpa_row(SLOT_U32(slot), head + (size_t)vn * D, lane);
            CPA_COMMIT();  // real or dummy
            if (lane == 0) logits[v] = s;
        }
    }
}

// ---------------------------------------------------------------------------
extern "C" void kernel_launch(void* const* d_in, const int* in_sizes, int n_in,
                              void* d_out, int out_size) {
    const int*   token     = (const int*)d_in[0];
    const float* state     = (const float*)d_in[1];
    const float* emb       = (const float*)d_in[2];
    const float* ln0_w     = (const float*)d_in[3];
    const float* ln0_b     = (const float*)d_in[4];
    const float* ln1_w     = (const float*)d_in[5];
    const float* ln1_b     = (const float*)d_in[6];
    const float* ln2_w     = (const float*)d_in[7];
    const float* ln2_b     = (const float*)d_in[8];
    const float* att_key   = (const float*)d_in[9];
    const float* att_value = (const float*)d_in[10];
    const float* att_recep = (const float*)d_in[11];
    const float* att_out   = (const float*)d_in[12];
    const float* tm_k      = (const float*)d_in[13];
    const float* tm_v      = (const float*)d_in[14];
    const float* tm_r      = (const float*)d_in[15];
    const float* t_first   = (const float*)d_in[16];
    const float* t_decay   = (const float*)d_in[17];
    const float* ffn_key   = (const float*)d_in[18];
    const float* ffn_value = (const float*)d_in[19];
    const float* ffn_recep = (const float*)d_in[20];
    const float* ffn_tm_k  = (const float*)d_in[21];
    const float* ffn_tm_r  = (const float*)d_in[22];
    const float* lnout_w   = (const float*)d_in[23];
    const float* lnout_b   = (const float*)d_in[24];
    const float* head      = (const float*)d_in[25];

    float* out = (float*)d_out;
    float* logits = out;
    float* state_out;
    if (out_size >= NV + NL * 5 * D) {
        state_out = out + NV;
    } else {
        void* p = nullptr;
        cudaGetSymbolAddress(&p, g_state_scratch);
        state_out = (float*)p;
    }

    static bool attr_set = false;
    if (!attr_set) {
        cudaFuncSetAttribute(rwkv_fused, cudaFuncAttributeMaxDynamicSharedMemorySize,
                             SMEM_DYN);
        attr_set = true;
    }

    rwkv_fused<<<GRID, NTH, SMEM_DYN>>>(token, state, emb, ln0_w, ln0_b,
                                        ln1_w, ln1_b, ln2_w, ln2_b,
                                        att_key, att_value, att_recep, att_out,
                                        tm_k, tm_v, tm_r, t_first, t_decay,
                                        ffn_key, ffn_value, ffn_recep,
                                        ffn_tm_k, ffn_tm_r,
                                        lnout_w, lnout_b, head,
                                        logits, state_out);
}

// round 13
// speedup vs baseline: 1.0716x; 1.0716x over previous
#include <cuda_runtime.h>
#include <cuda_bf16.h>

// RWKV single-token inference, fp32 — persistent kernel (148x256).
// R13: cp.async.bulk (TMA) weight streaming with per-warp/per-slot mbarriers
// (bypasses the per-16B-op L1tex wavefront cap of cp.async), fused single-pass
// LayerNorm, balanced row ownership, tight-spin grid barrier.
// D=1024, H=4096, L=24, V=50277.

#define D    1024
#define HD   4096
#define NL   24
#define NV   50277
#define GRID 148
#define NTH  256
#define NWARP 8
#define TOTW (GRID * NWARP)   // 1184

#define SBUF_F   4096                  // 16KB shared vector region (floats)
#define WSLOT_F  1024                  // 4KB slot
#define NSLOT    6
#define SMEM_DYN ((SBUF_F + NWARP * NSLOT * WSLOT_F) * 4)   // 208KB

__device__ __align__(16) float g_x[D];
__device__ __align__(16) float g_rwkv[D];
__device__ __align__(16) float g_kk[HD];
__device__ __align__(16) float g_r2[D];
__device__ __align__(16) float g_state_scratch[NL * 5 * D];
__device__ unsigned g_count;
__device__ unsigned g_gen;

__device__ __forceinline__ float warp_sum(float s) {
#pragma unroll
    for (int o = 16; o > 0; o >>= 1) s += __shfl_xor_sync(0xffffffffu, s, o);
    return s;
}

// Grid barrier (148 co-resident blocks), tight spin.
__device__ __forceinline__ void grid_barrier() {
    __syncthreads();
    if (threadIdx.x == 0) {
        unsigned gen;
        asm volatile("ld.global.relaxed.gpu.u32 %0, [%1];" : "=r"(gen) : "l"(&g_gen));
        unsigned old;
        asm volatile("atom.global.add.acq_rel.gpu.u32 %0, [%1], 1;"
                     : "=r"(old) : "l"(&g_count) : "memory");
        if (old == GRID - 1) {
            asm volatile("st.global.relaxed.gpu.u32 [%0], %1;" :: "l"(&g_count), "r"(0u) : "memory");
            asm volatile("st.global.release.gpu.u32 [%0], %1;" :: "l"(&g_gen), "r"(gen + 1u) : "memory");
        } else {
            unsigned cur;
            do {
                asm volatile("ld.global.acquire.gpu.u32 %0, [%1];" : "=r"(cur) : "l"(&g_gen) : "memory");
            } while (cur == gen);
        }
    }
    __syncthreads();
}

// One 4KB bulk copy global->shared, completion on mbar (lane 0 issues).
__device__ __forceinline__ void tma_issue(unsigned dst, const float* __restrict__ src,
                                          unsigned mbar, int lane) {
    if (lane == 0) {
        asm volatile("mbarrier.arrive.expect_tx.shared.b64 _, [%0], %1;"
                     :: "r"(mbar), "r"(4096u) : "memory");
        asm volatile("cp.async.bulk.shared::cluster.global.mbarrier::complete_tx::bytes "
                     "[%0], [%1], %2, [%3];"
                     :: "r"(dst), "l"(src), "r"(4096u), "r"(mbar) : "memory");
    }
}

__device__ __forceinline__ void mbar_wait(unsigned mbar, int phase) {
    asm volatile(
        "{\n\t.reg .pred P;\n"
        "WAIT_%=:\n\t"
        "mbarrier.try_wait.parity.acquire.cta.shared::cta.b64 P, [%0], %1, 0x989680;\n\t"
        "@P bra DONE_%=;\n\t"
        "bra WAIT_%=;\n"
        "DONE_%=:\n\t}"
        :: "r"(mbar), "r"((unsigned)phase) : "memory");
}

__device__ __forceinline__ float dot_ss(const float4* __restrict__ w4,
                                        const float4* __restrict__ v4, int lane) {
    float s = 0.f;
#pragma unroll
    for (int j = 0; j < 8; j++) {
        float4 a = w4[lane + 32 * j];
        float4 b = v4[lane + 32 * j];
        s = fmaf(a.x, b.x, s); s = fmaf(a.y, b.y, s);
        s = fmaf(a.z, b.z, s); s = fmaf(a.w, b.w, s);
    }
    return s;
}

// Fused single-pass LN over g_x: ONE block reduction for (sum, sumsq).
__device__ __forceinline__ void ln_fused(const float* __restrict__ w,
                                         const float* __restrict__ b,
                                         float* sred, float out[4]) {
    int t = threadIdx.x, warp = t >> 5, lane = t & 31;
    float4 xv = __ldcg((const float4*)g_x + t);
    float s = xv.x + xv.y + xv.z + xv.w;
    float q = xv.x * xv.x + xv.y * xv.y + xv.z * xv.z + xv.w * xv.w;
    __syncthreads();   // protect sred reuse
#pragma unroll
    for (int o = 16; o > 0; o >>= 1) {
        s += __shfl_xor_sync(0xffffffffu, s, o);
        q += __shfl_xor_sync(0xffffffffu, q, o);
    }
    if (lane == 0) { sred[warp] = s; sred[NWARP + warp] = q; }
    __syncthreads();
    float ts = 0.f, tq = 0.f;
#pragma unroll
    for (int ww = 0; ww < NWARP; ww++) { ts += sred[ww]; tq += sred[NWARP + ww]; }
    float mu = ts * (1.f / D);
    float var = tq * (1.f / D) - mu * mu;
    float rstd = rsqrtf(var + 1e-5f);
    float xa[4]; *(float4*)xa = xv;
    float wa[4], ba[4];
    *(float4*)wa = ((const float4*)w)[t];
    *(float4*)ba = ((const float4*)b)[t];
#pragma unroll
    for (int c = 0; c < 4; c++) out[c] = (xa[c] - mu) * rstd * wa[c] + ba[c];
}

__global__ __launch_bounds__(NTH, 1) void rwkv_fused(
    const int* __restrict__ token, const float* __restrict__ state,
    const float* __restrict__ emb,
    const float* __restrict__ ln0_w, const float* __restrict__ ln0_b,
    const float* __restrict__ ln1_w, const float* __restrict__ ln1_b,
    const float* __restrict__ ln2_w, const float* __restrict__ ln2_b,
    const float* __restrict__ kw, const float* __restrict__ vw,
    const float* __restrict__ rw, const float* __restrict__ ow,
    const float* __restrict__ mk, const float* __restrict__ mv,
    const float* __restrict__ mr,
    const float* __restrict__ tf, const float* __restrict__ td,
    const float* __restrict__ fkw, const float* __restrict__ fvw,
    const float* __restrict__ frw,
    const float* __restrict__ fmk, const float* __restrict__ fmr,
    const float* __restrict__ lnw, const float* __restrict__ lnb,
    const float* __restrict__ head,
    float* __restrict__ logits, float* __restrict__ state_out) {
    __shared__ float sred[2 * NWARP];
    __shared__ unsigned long long mbars[NWARP * NSLOT];
    extern __shared__ __align__(16) float dsm[];
    float* s_buf = dsm;                                             // 16KB

    const int t = threadIdx.x, warp = t >> 5, lane = t & 31, bid = blockIdx.x;
    const int wgS = warp * GRID + bid;          // 0..1183 (balanced over SMs)
    const bool rowact = (wgS < D);

    float* slots = dsm + SBUF_F + warp * (NSLOT * WSLOT_F);
    const unsigned slu = (unsigned)__cvta_generic_to_shared(slots);
    const unsigned mbu = (unsigned)__cvta_generic_to_shared(&mbars[warp * NSLOT]);
    const unsigned sl0 = slu, sl1 = slu + 4096u, sl2 = slu + 8192u,
                   sl3 = slu + 12288u, sl4 = slu + 16384u, sl5 = slu + 20480u;
    const unsigned mb0 = mbu, mb1 = mbu + 8u, mb2 = mbu + 16u,
                   mb3 = mbu + 24u, mb4 = mbu + 32u, mb5 = mbu + 40u;
    const float4* q0 = (const float4*)slots;
    const float4* q1 = (const float4*)(slots + WSLOT_F);
    const float4* q2 = (const float4*)(slots + 2 * WSLOT_F);
    const float4* q3 = (const float4*)(slots + 3 * WSLOT_F);
    const float4* q4 = (const float4*)(slots + 4 * WSLOT_F);
    const float4* q5 = (const float4*)(slots + 5 * WSLOT_F);
    int p0 = 0, p1 = 0, p2 = 0, p3 = 0, p4 = 0, p5 = 0;

#define ISSUE(K, SRC) tma_issue(sl##K, (SRC), mb##K, lane)
#define WAITF(K)      do { mbar_wait(mb##K, p##K); p##K ^= 1; } while (0)

    // init mbarriers (count=1 each)
    if (t < NWARP * NSLOT) {
        unsigned a = (unsigned)__cvta_generic_to_shared(&mbars[t]);
        asm volatile("mbarrier.init.shared.b64 [%0], %1;" :: "r"(a), "r"(1u) : "memory");
    }
    __syncthreads();
    asm volatile("fence.proxy.async.shared::cta;" ::: "memory");

    // C-phase unit ids
    const int u1 = wgS + TOTW, u2 = wgS + 2 * TOTW, u3 = wgS + 3 * TOTW, u4 = wgS + 4 * TOTW;
    const bool u3fk = (u3 < HD);
    const bool hasC5 = (u4 < HD + D);   // wgS < 384

    // ---- embed: block 0 computes g_x = LN0(emb[token]) (fused LN) ----
    if (bid == 0) {
        float4 xv = ((const float4*)(emb + (size_t)token[0] * D))[t];
        float s = xv.x + xv.y + xv.z + xv.w;
        float q = xv.x * xv.x + xv.y * xv.y + xv.z * xv.z + xv.w * xv.w;
#pragma unroll
        for (int o = 16; o > 0; o >>= 1) {
            s += __shfl_xor_sync(0xffffffffu, s, o);
            q += __shfl_xor_sync(0xffffffffu, q, o);
        }
        if (lane == 0) { sred[warp] = s; sred[NWARP + warp] = q; }
        __syncthreads();
        float ts = 0.f, tq = 0.f;
#pragma unroll
        for (int ww = 0; ww < NWARP; ww++) { ts += sred[ww]; tq += sred[NWARP + ww]; }
        float mu = ts * (1.f / D);
        float var = tq * (1.f / D) - mu * mu;
        float rstd = rsqrtf(var + 1e-5f);
        float4 wv = ((const float4*)ln0_w)[t];
        float4 bv = ((const float4*)ln0_b)[t];
        float4 o;
        o.x = (xv.x - mu) * rstd * wv.x + bv.x;
        o.y = (xv.y - mu) * rstd * wv.y + bv.y;
        o.z = (xv.z - mu) * rstd * wv.z + bv.z;
        o.w = (xv.w - mu) * rstd * wv.w + bv.w;
        ((float4*)g_x)[t] = o;
    }

    for (int l = 0; l < NL; l++) {
        const size_t lo = (size_t)l * D;
        const size_t sb = (size_t)l * 5 * D;
        const float* fk_base = fkw + (size_t)l * HD * D;
        const float* fr_base = frw + lo * D;
        const float* fv_row  = fvw + (size_t)l * D * HD + (size_t)wgS * HD;

        // ---- layer top: issue k,v,r,ow (rowact) and u0,u1 (all) ----
        if (rowact) {
            ISSUE(0, kw + lo * D + (size_t)wgS * D);
            ISSUE(1, vw + lo * D + (size_t)wgS * D);
            ISSUE(2, rw + lo * D + (size_t)wgS * D);
            ISSUE(3, ow + lo * D + (size_t)wgS * D);
        }
        ISSUE(4, fk_base + (size_t)wgS * D);
        ISSUE(5, fk_base + (size_t)u1 * D);

        // ================= Phase A: time mixing =================
        grid_barrier();   // g_x final
        {
            float xn4[4];
            ln_fused(ln1_w + lo, ln1_b + lo, sred, xn4);
            float mka[4], mva[4], mra[4], sxa[4];
            *(float4*)mka = ((const float4*)(mk + lo))[t];
            *(float4*)mva = ((const float4*)(mv + lo))[t];
            *(float4*)mra = ((const float4*)(mr + lo))[t];
            *(float4*)sxa = ((const float4*)(state + sb + D))[t];  // sx_att
            int base = 4 * t;
#pragma unroll
            for (int c = 0; c < 4; c++) {
                float xn = xn4[c];
                s_buf[base + c]         = xn * mka[c] + sxa[c] * (1.f - mka[c]);
                s_buf[D + base + c]     = xn * mva[c] + sxa[c] * (1.f - mva[c]);
                s_buf[2 * D + base + c] = xn * mra[c] + sxa[c] * (1.f - mra[c]);
                if (bid == 0) state_out[sb + D + base + c] = xn;   // state row 1
            }
            __syncthreads();

            if (rowact) {
                // epilogue scalars early (hide latency under dots)
                float aa = 0.f, bb = 0.f, pp = 0.f, tfv = 0.f, tdv = 0.f;
                if (lane == 0) {
                    aa  = state[sb + 2 * D + wgS];
                    bb  = state[sb + 3 * D + wgS];
                    pp  = state[sb + 4 * D + wgS];
                    tfv = tf[lo + wgS];
                    tdv = td[lo + wgS];
                }
                WAITF(0);
                float sk = warp_sum(dot_ss(q0, (const float4*)s_buf, lane));
                WAITF(1);
                float sv = warp_sum(dot_ss(q1, (const float4*)(s_buf + D), lane));
                WAITF(2);
                float sr = warp_sum(dot_ss(q2, (const float4*)(s_buf + 2 * D), lane));

                if (lane == 0) {
                    float k = sk, v = sv;
                    float rs = 1.f / (1.f + expf(-sr));
                    float ww = tfv + k;
                    float qq = fmaxf(pp, ww);
                    float e1 = expf(pp - qq);
                    float e2 = expf(ww - qq);
                    g_rwkv[wgS] = rs * (e1 * aa + e2 * v) / (e1 * bb + e2);
                    float ww2 = pp + tdv;
                    float qq2 = fmaxf(ww2, k);
                    float e1b = expf(ww2 - qq2);
                    float e2b = expf(k - qq2);
                    state_out[sb + 2 * D + wgS] = e1b * aa + e2b * v;
                    state_out[sb + 3 * D + wgS] = e1b * bb + e2b;
                    state_out[sb + 4 * D + wgS] = qq2;
                }
            }
            // A tail: issue u2 -> s0, u3 -> s1 (all warps)
            ISSUE(0, fk_base + (size_t)u2 * D);
            ISSUE(1, u3fk ? fk_base + (size_t)u3 * D
                          : fr_base + (size_t)(u3 - HD) * D);
        }

        // ================= Phase B: x += ow @ rwkv =================
        grid_barrier();   // g_rwkv complete
        {
            ((float4*)s_buf)[t] = __ldcg((const float4*)g_rwkv + t);
            __syncthreads();
            if (rowact) {
                WAITF(3);
                float s = warp_sum(dot_ss(q3, (const float4*)s_buf, lane));
                if (lane == 0) g_x[wgS] = __ldcg(g_x + wgS) + s;
            }
            // B tail: issue u4 -> s2 (if any)
            if (hasC5) ISSUE(2, fr_base + (size_t)(u4 - HD) * D);
        }

        // ================= Phase C: channel mix 1 =================
        grid_barrier();   // g_x updated
        {
            float xn4[4];
            ln_fused(ln2_w + lo, ln2_b + lo, sred, xn4);
            float mka[4], mra[4], sxa[4];
            *(float4*)mka = ((const float4*)(fmk + lo))[t];
            *(float4*)mra = ((const float4*)(fmr + lo))[t];
            *(float4*)sxa = ((const float4*)(state + sb))[t];      // sx_ffn
            int base = 4 * t;
#pragma unroll
            for (int c = 0; c < 4; c++) {
                float xn = xn4[c];
                s_buf[base + c]     = xn * mka[c] + sxa[c] * (1.f - mka[c]);
                s_buf[D + base + c] = xn * mra[c] + sxa[c] * (1.f - mra[c]);
                if (bid == 0) state_out[sb + base + c] = xn;       // state row 0
            }
            __syncthreads();

            const float4* xk4 = (const float4*)s_buf;
            const float4* xr4 = (const float4*)(s_buf + D);

            WAITF(4);   // u0
            {
                float s = warp_sum(dot_ss(q4, xk4, lane));
                if (lane == 0) { float rl = fmaxf(s, 0.f); g_kk[wgS] = rl * rl; }
            }
            if (rowact) ISSUE(4, fv_row);                 // fv chunk 0

            WAITF(5);   // u1
            {
                float s = warp_sum(dot_ss(q5, xk4, lane));
                if (lane == 0) { float rl = fmaxf(s, 0.f); g_kk[u1] = rl * rl; }
            }
            if (rowact) ISSUE(5, fv_row + 1024);          // chunk 1

            WAITF(0);   // u2
            {
                float s = warp_sum(dot_ss(q0, xk4, lane));
                if (lane == 0) { float rl = fmaxf(s, 0.f); g_kk[u2] = rl * rl; }
            }
            if (rowact) ISSUE(0, fv_row + 2048);          // chunk 2

            WAITF(1);   // u3
            {
                float s = warp_sum(dot_ss(q1, u3fk ? xk4 : xr4, lane));
                if (lane == 0) {
                    if (u3fk) { float rl = fmaxf(s, 0.f); g_kk[u3] = rl * rl; }
                    else g_r2[u3 - HD] = 1.f / (1.f + expf(-s));
                }
            }
            if (rowact) ISSUE(1, fv_row + 3072);          // chunk 3

            if (hasC5) {
                WAITF(2);   // u4
                float s = warp_sum(dot_ss(q2, xr4, lane));
                if (lane == 0) g_r2[u4 - HD] = 1.f / (1.f + expf(-s));
            }
        }

        // ================= Phase D: x += r2 * (fvw @ kk) =================
        grid_barrier();   // g_kk, g_r2 complete
        {
#pragma unroll
            for (int j = 0; j < 4; j++)
                ((float4*)s_buf)[t + NTH * j] = __ldcg((const float4*)g_kk + t + NTH * j);
            __syncthreads();
            if (rowact) {
                const float4* k4 = (const float4*)s_buf;
                WAITF(4);
                float s = dot_ss(q4, k4, lane);
                WAITF(5);
                s += dot_ss(q5, k4 + 256, lane);
                WAITF(0);
                s += dot_ss(q0, k4 + 512, lane);
                WAITF(1);
                s += dot_ss(q1, k4 + 768, lane);
                s = warp_sum(s);
                if (lane == 0) g_x[wgS] = __ldcg(g_x + wgS) + __ldcg(g_r2 + wgS) * s;
            }
        }
    }

    // ================= Head: logits = head @ LN(x) =================
    ISSUE(0, head + (size_t)(wgS)            * D);
    ISSUE(1, head + (size_t)(wgS + TOTW)     * D);
    ISSUE(2, head + (size_t)(wgS + 2 * TOTW) * D);
    ISSUE(3, head + (size_t)(wgS + 3 * TOTW) * D);
    ISSUE(4, head + (size_t)(wgS + 4 * TOTW) * D);
    ISSUE(5, head + (size_t)(wgS + 5 * TOTW) * D);   // 7103 < NV, always valid
    grid_barrier();   // g_x final
    {
        float xn4[4];
        ln_fused(lnw, lnb, sred, xn4);
        int base = 4 * t;
#pragma unroll
        for (int c = 0; c < 4; c++) s_buf[base + c] = xn4[c];
        __syncthreads();

        const float4* x4 = (const float4*)s_buf;
#define HSTEP(J) { int v = v0 + J * TOTW; if (v < NV) { \
            WAITF(J); \
            float s = warp_sum(dot_ss(q##J, x4, lane)); \
            int vn = v + NSLOT * TOTW; \
            if (vn < NV) ISSUE(J, head + (size_t)vn * D); \
            if (lane == 0) logits[v] = s; } }
        for (int v0 = wgS; v0 < NV; v0 += NSLOT * TOTW) {
            HSTEP(0) HSTEP(1) HSTEP(2) HSTEP(3) HSTEP(4) HSTEP(5)
        }
#undef HSTEP
    }
}

// ---------------------------------------------------------------------------
extern "C" void kernel_launch(void* const* d_in, const int* in_sizes, int n_in,
                              void* d_out, int out_size) {
    const int*   token     = (const int*)d_in[0];
    const float* state     = (const float*)d_in[1];
    const float* emb       = (const float*)d_in[2];
    const float* ln0_w     = (const float*)d_in[3];
    const float* ln0_b     = (const float*)d_in[4];
    const float* ln1_w     = (const float*)d_in[5];
    const float* ln1_b     = (const float*)d_in[6];
    const float* ln2_w     = (const float*)d_in[7];
    const float* ln2_b     = (const float*)d_in[8];
    const float* att_key   = (const float*)d_in[9];
    const float* att_value = (const float*)d_in[10];
    const float* att_recep = (const float*)d_in[11];
    const float* att_out   = (const float*)d_in[12];
    const float* tm_k      = (const float*)d_in[13];
    const float* tm_v      = (const float*)d_in[14];
    const float* tm_r      = (const float*)d_in[15];
    const float* t_first   = (const float*)d_in[16];
    const float* t_decay   = (const float*)d_in[17];
    const float* ffn_key   = (const float*)d_in[18];
    const float* ffn_value = (const float*)d_in[19];
    const float* ffn_recep = (const float*)d_in[20];
    const float* ffn_tm_k  = (const float*)d_in[21];
    const float* ffn_tm_r  = (const float*)d_in[22];
    const float* lnout_w   = (const float*)d_in[23];
    const float* lnout_b   = (const float*)d_in[24];
    const float* head      = (const float*)d_in[25];

    float* out = (float*)d_out;
    float* logits = out;
    float* state_out;
    if (out_size >= NV + NL * 5 * D) {
        state_out = out + NV;
    } else {
        void* p = nullptr;
        cudaGetSymbolAddress(&p, g_state_scratch);
        state_out = (float*)p;
    }

    static bool attr_set = false;
    if (!attr_set) {
        cudaFuncSetAttribute(rwkv_fused, cudaFuncAttributeMaxDynamicSharedMemorySize,
                             SMEM_DYN);
        attr_set = true;
    }

    rwkv_fused<<<GRID, NTH, SMEM_DYN>>>(token, state, emb, ln0_w, ln0_b,
                                        ln1_w, ln1_b, ln2_w, ln2_b,
                                        att_key, att_value, att_recep, att_out,
                                        tm_k, tm_v, tm_r, t_first, t_decay,
                                        ffn_key, ffn_value, ffn_recep,
                                        ffn_tm_k, ffn_tm_r,
                                        lnout_w, lnout_b, head,
                                        logits, state_out);
}